// round 7
// baseline (speedup 1.0000x reference)
#include <cuda_runtime.h>

#define Bb 16
#define Ss 4096
#define Hh 1024
#define NN 2048
#define DWw 50
#define OD (Hh + DWw)   // 1074

#define WPB 32                // words per block
#define NGRP (NN / WPB)       // 64 groups per batch
#define NCH_W 8               // lastw chunks per batch

__device__ float g_part[Bb][NGRP][Hh];   // per-block prefix maxes (4MB)
__device__ int   g_start[Bb][NN + 1];
__device__ int   g_cnt[Bb];

__device__ __forceinline__ void atomicMaxF(float* addr, float val) {
    if (val >= 0.f) atomicMax((int*)addr, __float_as_int(val));
    else            atomicMin((unsigned int*)addr, __float_as_uint(val));
}

__device__ __forceinline__ float4 fmax4(float4 a, float4 b) {
    a.x = fmaxf(a.x, b.x); a.y = fmaxf(a.y, b.y);
    a.z = fmaxf(a.z, b.z); a.w = fmaxf(a.w, b.w);
    return a;
}

// Pass 1: word-span boundaries from sorted seg_ids (int4); init last-row
// word-part to -inf (lastw atomics fold into it); reset arrival counters.
__global__ void prep_kernel(const int* __restrict__ seg,
                            const int* __restrict__ ns_arr,
                            float* __restrict__ out) {
    int b = blockIdx.x;
    int i = blockIdx.y * 256 + threadIdx.x;          // int4 index 0..1023
    const int4* s4 = (const int4*)(seg + (long)b * Ss);
    int4 v = s4[i];
    int s = i * 4;
    int prev = (s == 0) ? -1 : __ldg(seg + (long)b * Ss + s - 1);
    if (v.x != prev) g_start[b][v.x] = s;
    if (v.y != v.x)  g_start[b][v.y] = s + 1;
    if (v.z != v.y)  g_start[b][v.z] = s + 2;
    if (v.w != v.z)  g_start[b][v.w] = s + 3;
    if (s + 3 == Ss - 1) g_start[b][v.w + 1] = Ss;   // sentinel end

    if (blockIdx.y == 0) {
        float ninf = __int_as_float(0xFF800000);
        int n = ns_arr[b] - 1;
        if (threadIdx.x < DWw)
            out[((long)b * NN + n) * OD + Hh + threadIdx.x] = ninf;
        if (threadIdx.x == 0) g_cnt[b] = 0;
    }
}

// Pass 2 (single big kernel): 32 consecutive words per block (contiguous ctx
// streaming) + concat. Prefix rows (< ns-1) fold into a register -> plain
// store to g_part. Last-arriving block per batch reduces the partials and
// writes the last-word row's ctx part. lastw chunks atomic into the row's
// word-emb part.
__global__ void __launch_bounds__(256)
fused_kernel(const float* __restrict__ ctx,
             const float* __restrict__ wemb,
             const int* __restrict__ ns_arr,
             float* __restrict__ out) {
    int bx = blockIdx.x;
    int b  = blockIdx.y;
    int t  = threadIdx.x;            // 0..255, owns channels 4t..4t+3
    int ns = ns_arr[b];
    float ninf = __int_as_float(0xFF800000);

    if (bx < NGRP) {
        int n0 = bx * WPB;
        __shared__ int sbound[WPB + 1];
        if (t <= WPB) sbound[t] = g_start[b][min(n0 + t, NN)];
        __syncthreads();

        float4 blockAcc = make_float4(ninf, ninf, ninf, ninf);

        for (int w = 0; w < WPB; w++) {
            int n = n0 + w;
            float* orow = out + ((long)b * NN + n) * OD;
            float2* o2 = (float2*)orow;   // rows 8B-aligned (4296B stride)

            if (n >= ns) {                // padding: zero-fill (out is poisoned)
                for (int i = t; i < OD / 2; i += 256) o2[i] = make_float2(0.f, 0.f);
                continue;
            }
            if (n == ns - 1) continue;    // special row handled below

            int start = sbound[w];
            int end   = sbound[w + 1];
            int cnt = end - start;
            int k = ns - 1 - start;       // rows counting toward last_ctx
            k = max(0, min(cnt, k));

            const float4* crow = (const float4*)(ctx + ((long)b * Ss + start) * Hh);
            float4 acc = crow[t];
            int r = 1;
            if (k > 0) {
#pragma unroll 4
                for (; r < k; r++) acc = fmax4(acc, crow[(long)r * (Hh / 4) + t]);
                blockAcc = fmax4(blockAcc, acc);
            }
#pragma unroll 4
            for (; r < cnt; r++) acc = fmax4(acc, crow[(long)r * (Hh / 4) + t]);

            o2[2 * t]     = make_float2(acc.x, acc.y);
            o2[2 * t + 1] = make_float2(acc.z, acc.w);
            if (t < DWw) orow[Hh + t] = wemb[((long)b * NN + n) * DWw + t];
        }
        ((float4*)g_part[b][bx])[t] = blockAcc;   // plain store, no atomics

        // decoupled completion: last block per batch folds all partials
        __threadfence();
        __shared__ int is_last;
        __syncthreads();
        if (t == 0) is_last = (atomicAdd(&g_cnt[b], 1) == NGRP - 1);
        __syncthreads();
        if (is_last) {
            __threadfence();
            float4 a = make_float4(ninf, ninf, ninf, ninf);
#pragma unroll 8
            for (int g = 0; g < NGRP; g++)
                a = fmax4(a, ((const float4*)g_part[b][g])[t]);
            float2* o2 = (float2*)(out + ((long)b * NN + ns - 1) * OD);
            o2[2 * t]     = make_float2(a.x, a.y);
            o2[2 * t + 1] = make_float2(a.z, a.w);
        }
        return;
    }

    // lastw: max over words 0..ns-1 of word_emb -> atomics into out row
    int rc = bx - NGRP;
    if (t >= DWw) return;
    int per = (ns + NCH_W - 1) / NCH_W;
    int r0 = rc * per;
    int r1 = min(ns, r0 + per);
    if (r0 >= r1) return;
    float acc = wemb[((long)b * NN + r0) * DWw + t];
#pragma unroll 4
    for (int r = r0 + 1; r < r1; r++) {
        acc = fmaxf(acc, wemb[((long)b * NN + r) * DWw + t]);
    }
    atomicMaxF(out + ((long)b * NN + ns - 1) * OD + Hh + t, acc);
}

extern "C" void kernel_launch(void* const* d_in, const int* in_sizes, int n_in,
                              void* d_out, int out_size) {
    const float* ctx  = (const float*)d_in[0];   // [B, S, H]
    const float* wemb = (const float*)d_in[1];   // [B, N, DW]
    const int*   seg  = (const int*)d_in[2];     // [B, S]
    const int*   ns   = (const int*)d_in[3];     // [B]
    float* out = (float*)d_out;                  // [B, N, H+DW]

    prep_kernel<<<dim3(Bb, 4), 256>>>(seg, ns, out);
    fused_kernel<<<dim3(NGRP + NCH_W, Bb), 256>>>(ctx, wemb, ns, out);
}

// round 8
// speedup vs baseline: 1.0638x; 1.0638x over previous
#include <cuda_runtime.h>

#define Bb 16
#define Ss 4096
#define Hh 1024
#define NN 2048
#define DWw 50
#define OD (Hh + DWw)   // 1074

#define WPB 16                // words per block (R6-proven granularity)
#define NGRP (NN / WPB)       // 128 groups per batch
#define NCH_W 8               // lastw chunks per batch

__device__ float g_part[Bb][NGRP][Hh];   // per-block prefix maxes (8MB)
__device__ int   g_start[Bb][NN + 1];
__device__ int   g_cnt[Bb];

__device__ __forceinline__ void atomicMaxF(float* addr, float val) {
    if (val >= 0.f) atomicMax((int*)addr, __float_as_int(val));
    else            atomicMin((unsigned int*)addr, __float_as_uint(val));
}

__device__ __forceinline__ float4 fmax4(float4 a, float4 b) {
    a.x = fmaxf(a.x, b.x); a.y = fmaxf(a.y, b.y);
    a.z = fmaxf(a.z, b.z); a.w = fmaxf(a.w, b.w);
    return a;
}

// Pass 1: word-span boundaries from sorted seg_ids (int4); init last-row
// word-part to -inf (lastw atomics fold into it); reset arrival counters.
__global__ void prep_kernel(const int* __restrict__ seg,
                            const int* __restrict__ ns_arr,
                            float* __restrict__ out) {
    int b = blockIdx.x;
    int i = blockIdx.y * 256 + threadIdx.x;          // int4 index 0..1023
    const int4* s4 = (const int4*)(seg + (long)b * Ss);
    int4 v = s4[i];
    int s = i * 4;
    int prev = (s == 0) ? -1 : __ldg(seg + (long)b * Ss + s - 1);
    if (v.x != prev) g_start[b][v.x] = s;
    if (v.y != v.x)  g_start[b][v.y] = s + 1;
    if (v.z != v.y)  g_start[b][v.z] = s + 2;
    if (v.w != v.z)  g_start[b][v.w] = s + 3;
    if (s + 3 == Ss - 1) g_start[b][v.w + 1] = Ss;   // sentinel end

    if (blockIdx.y == 0) {
        float ninf = __int_as_float(0xFF800000);
        int n = ns_arr[b] - 1;
        if (threadIdx.x < DWw)
            out[((long)b * NN + n) * OD + Hh + threadIdx.x] = ninf;
        if (threadIdx.x == 0) g_cnt[b] = 0;
    }
}

// Pass 2 (single big kernel): 16 consecutive words per block (contiguous ctx
// streaming) + concat. Prefix rows (< ns-1) fold into a register -> plain
// store to g_part. Last-arriving block per batch reduces the partials in the
// wave tail and writes the last-word row's ctx part. lastw chunks atomic
// into the row's word-emb part.
__global__ void __launch_bounds__(256)
fused_kernel(const float* __restrict__ ctx,
             const float* __restrict__ wemb,
             const int* __restrict__ ns_arr,
             float* __restrict__ out) {
    int bx = blockIdx.x;
    int b  = blockIdx.y;
    int t  = threadIdx.x;            // 0..255, owns channels 4t..4t+3
    int ns = ns_arr[b];
    float ninf = __int_as_float(0xFF800000);

    if (bx < NGRP) {
        int n0 = bx * WPB;
        __shared__ int sbound[WPB + 1];
        if (t <= WPB) sbound[t] = g_start[b][min(n0 + t, NN)];
        __syncthreads();

        float4 blockAcc = make_float4(ninf, ninf, ninf, ninf);

        for (int w = 0; w < WPB; w++) {
            int n = n0 + w;
            float* orow = out + ((long)b * NN + n) * OD;
            float2* o2 = (float2*)orow;   // rows 8B-aligned (4296B stride)

            if (n >= ns) {                // padding: zero-fill (out is poisoned)
                for (int i = t; i < OD / 2; i += 256) o2[i] = make_float2(0.f, 0.f);
                continue;
            }
            if (n == ns - 1) continue;    // special row handled below

            int start = sbound[w];
            int end   = sbound[w + 1];
            int cnt = end - start;
            int k = ns - 1 - start;       // rows counting toward last_ctx
            k = max(0, min(cnt, k));

            const float4* crow = (const float4*)(ctx + ((long)b * Ss + start) * Hh);
            float4 acc = crow[t];
            int r = 1;
            if (k > 0) {
#pragma unroll 4
                for (; r < k; r++) acc = fmax4(acc, crow[(long)r * (Hh / 4) + t]);
                blockAcc = fmax4(blockAcc, acc);
            }
#pragma unroll 4
            for (; r < cnt; r++) acc = fmax4(acc, crow[(long)r * (Hh / 4) + t]);

            o2[2 * t]     = make_float2(acc.x, acc.y);
            o2[2 * t + 1] = make_float2(acc.z, acc.w);
            if (t < DWw) orow[Hh + t] = wemb[((long)b * NN + n) * DWw + t];
        }
        ((float4*)g_part[b][bx])[t] = blockAcc;   // plain store, no atomics

        // decoupled completion: last-arriving block per batch folds partials
        __threadfence();
        __shared__ int is_last;
        __syncthreads();
        if (t == 0) is_last = (atomicAdd(&g_cnt[b], 1) == NGRP - 1);
        __syncthreads();
        if (is_last) {
            __threadfence();
            float4 a = make_float4(ninf, ninf, ninf, ninf);
#pragma unroll 8
            for (int g = 0; g < NGRP; g++)
                a = fmax4(a, ((const float4*)g_part[b][g])[t]);
            float2* o2 = (float2*)(out + ((long)b * NN + ns - 1) * OD);
            o2[2 * t]     = make_float2(a.x, a.y);
            o2[2 * t + 1] = make_float2(a.z, a.w);
        }
        return;
    }

    // lastw: max over words 0..ns-1 of word_emb -> atomics into out row
    int rc = bx - NGRP;
    if (t >= DWw) return;
    int per = (ns + NCH_W - 1) / NCH_W;
    int r0 = rc * per;
    int r1 = min(ns, r0 + per);
    if (r0 >= r1) return;
    float acc = wemb[((long)b * NN + r0) * DWw + t];
#pragma unroll 4
    for (int r = r0 + 1; r < r1; r++) {
        acc = fmaxf(acc, wemb[((long)b * NN + r) * DWw + t]);
    }
    atomicMaxF(out + ((long)b * NN + ns - 1) * OD + Hh + t, acc);
}

extern "C" void kernel_launch(void* const* d_in, const int* in_sizes, int n_in,
                              void* d_out, int out_size) {
    const float* ctx  = (const float*)d_in[0];   // [B, S, H]
    const float* wemb = (const float*)d_in[1];   // [B, N, DW]
    const int*   seg  = (const int*)d_in[2];     // [B, S]
    const int*   ns   = (const int*)d_in[3];     // [B]
    float* out = (float*)d_out;                  // [B, N, H+DW]

    prep_kernel<<<dim3(Bb, 4), 256>>>(seg, ns, out);
    fused_kernel<<<dim3(NGRP + NCH_W, Bb), 256>>>(ctx, wemb, ns, out);
}

// round 9
// speedup vs baseline: 1.1284x; 1.0607x over previous
#include <cuda_runtime.h>

#define Bb 16
#define Ss 4096
#define Hh 1024
#define NN 2048
#define DWw 50
#define OD (Hh + DWw)   // 1074

#define WPB 16                // words per block
#define NGRP (NN / WPB)       // 128 groups per batch
#define NCH_W 8               // lastw chunks per batch
#define RCH 8                 // reduce chunks per batch

__device__ float g_part[Bb][NGRP][Hh];   // per-block prefix maxes (8MB)
__device__ int   g_start[Bb][NN + 1];

__device__ __forceinline__ void atomicMaxF(float* addr, float val) {
    if (val >= 0.f) atomicMax((int*)addr, __float_as_int(val));
    else            atomicMin((unsigned int*)addr, __float_as_uint(val));
}

__device__ __forceinline__ float4 fmax4(float4 a, float4 b) {
    a.x = fmaxf(a.x, b.x); a.y = fmaxf(a.y, b.y);
    a.z = fmaxf(a.z, b.z); a.w = fmaxf(a.w, b.w);
    return a;
}

// Pass 1: word-span boundaries from sorted seg_ids (int4); fill tail of
// g_start with Ss so every sbound read is valid; init last-row word-part.
__global__ void prep_kernel(const int* __restrict__ seg,
                            const int* __restrict__ ns_arr,
                            float* __restrict__ out) {
    int b = blockIdx.x;
    int i = blockIdx.y * 256 + threadIdx.x;          // int4 index 0..1023
    const int4* s4 = (const int4*)(seg + (long)b * Ss);
    int4 v = s4[i];
    int s = i * 4;
    int prev = (s == 0) ? -1 : __ldg(seg + (long)b * Ss + s - 1);
    if (v.x != prev) g_start[b][v.x] = s;
    if (v.y != v.x)  g_start[b][v.y] = s + 1;
    if (v.z != v.y)  g_start[b][v.z] = s + 2;
    if (v.w != v.z)  g_start[b][v.w] = s + 3;

    if (blockIdx.y == 0) {
        int ns = ns_arr[b];
        // words ns-1..NN have no span: start = Ss (also the sentinel end)
        for (int n = ns - 1 + threadIdx.x; n <= NN; n += 256)
            g_start[b][n] = Ss;
        float ninf = __int_as_float(0xFF800000);
        if (threadIdx.x < DWw)
            out[((long)b * NN + ns - 1) * OD + Hh + threadIdx.x] = ninf;
    }
}

// Pass 2: row-streaming segmented max. Each block owns the contiguous
// subword rows of 16 consecutive words; loads stream with high MLP, words
// flush on boundary. blockAcc (rows < ns-1) -> g_part plain store.
__global__ void __launch_bounds__(256)
fused_kernel(const float* __restrict__ ctx,
             const float* __restrict__ wemb,
             const int* __restrict__ ns_arr,
             float* __restrict__ out) {
    int bx = blockIdx.x;
    int b  = blockIdx.y;
    int t  = threadIdx.x;            // 0..255, owns channels 4t..4t+3
    int ns = ns_arr[b];
    float ninf = __int_as_float(0xFF800000);
    float4 ninf4 = make_float4(ninf, ninf, ninf, ninf);

    if (bx < NGRP) {
        int n0 = bx * WPB;
        __shared__ int sbound[WPB + 2];
        if (t <= WPB) sbound[t] = g_start[b][n0 + t];
        if (t == WPB + 1) sbound[WPB + 1] = 0x7fffffff;
        __syncthreads();

        // padding rows (n >= ns): zero-fill (out is poisoned)
        for (int w = max(0, ns - n0); w < WPB; w++) {
            float2* o2 = (float2*)(out + ((long)b * NN + n0 + w) * OD);
            for (int i = t; i < OD / 2; i += 256) o2[i] = make_float2(0.f, 0.f);
        }
        // word-emb concat for real (non-special) words
        if (t < DWw) {
            int wend = min(WPB, ns - 1 - n0);
            for (int w = 0; w < wend; w++)
                out[((long)b * NN + n0 + w) * OD + Hh + t] =
                    wemb[((long)b * NN + n0 + w) * DWw + t];
        }

        int r0 = sbound[0];
        int r1 = sbound[WPB];
        const float4* cbase = (const float4*)(ctx + (long)b * Ss * Hh);
        float4 acc = ninf4;
        float4 blockAcc = ninf4;
        int w = 0;
        int next_end = sbound[1];
        int lim = ns - 1;                 // rows < lim feed last_ctx

#pragma unroll 4
        for (int r = r0; r < r1; r++) {
            float4 v = cbase[(long)r * (Hh / 4) + t];
            acc = fmax4(acc, v);
            if (r < lim) blockAcc = fmax4(blockAcc, v);
            if (r + 1 == next_end) {      // word n0+w complete -> flush
                float2* o2 = (float2*)(out + ((long)b * NN + n0 + w) * OD);
                o2[2 * t]     = make_float2(acc.x, acc.y);
                o2[2 * t + 1] = make_float2(acc.z, acc.w);
                acc = ninf4;
                w++;
                next_end = sbound[w + 1];
            }
        }
        ((float4*)g_part[b][bx])[t] = blockAcc;   // plain store, no atomics
        return;
    }

    // lastw: max over words 0..ns-1 of word_emb -> atomics into out row
    int rc = bx - NGRP;
    if (t >= DWw) return;
    int per = (ns + NCH_W - 1) / NCH_W;
    int r0 = rc * per;
    int r1 = min(ns, r0 + per);
    if (r0 >= r1) return;
    float acc = wemb[((long)b * NN + r0) * DWw + t];
#pragma unroll 4
    for (int r = r0 + 1; r < r1; r++) {
        acc = fmaxf(acc, wemb[((long)b * NN + r) * DWw + t]);
    }
    atomicMaxF(out + ((long)b * NN + ns - 1) * OD + Hh + t, acc);
}

// Pass 3: reduce g_part chunks into the last-word output row's ctx part.
__global__ void reduce_kernel(const int* __restrict__ ns_arr,
                              float* __restrict__ out) {
    int c = blockIdx.x;              // 0..RCH-1
    int b = blockIdx.y;
    int t = threadIdx.x;             // 0..255
    float ninf = __int_as_float(0xFF800000);
    float4 a = make_float4(ninf, ninf, ninf, ninf);
    int g0 = c * (NGRP / RCH);
#pragma unroll 4
    for (int g = g0; g < g0 + NGRP / RCH; g++) {
        a = fmax4(a, ((const float4*)g_part[b][g])[t]);
    }
    int n = ns_arr[b] - 1;
    float* dst = out + ((long)b * NN + n) * OD + 4 * t;
    atomicMaxF(dst + 0, a.x);
    atomicMaxF(dst + 1, a.y);
    atomicMaxF(dst + 2, a.z);
    atomicMaxF(dst + 3, a.w);
}

extern "C" void kernel_launch(void* const* d_in, const int* in_sizes, int n_in,
                              void* d_out, int out_size) {
    const float* ctx  = (const float*)d_in[0];   // [B, S, H]
    const float* wemb = (const float*)d_in[1];   // [B, N, DW]
    const int*   seg  = (const int*)d_in[2];     // [B, S]
    const int*   ns   = (const int*)d_in[3];     // [B]
    float* out = (float*)d_out;                  // [B, N, H+DW]

    prep_kernel<<<dim3(Bb, 4), 256>>>(seg, ns, out);
    fused_kernel<<<dim3(NGRP + NCH_W, Bb), 256>>>(ctx, wemb, ns, out);
    reduce_kernel<<<dim3(RCH, Bb), 256>>>(ns, out);
}